// round 6
// baseline (speedup 1.0000x reference)
#include <cuda_runtime.h>
#include <math.h>

#define NN 100000
#define EE 1600000
#define ET 1700000   // EE + NN self loops
#define DIN 128
#define FF 64
#define GG 512
#define CC 10

// ---------------- scratch (device globals; no allocation) ----------------
__device__ float g_h[NN * FF];     // current layer transformed features
__device__ float g_acc[NN * FF];   // attention-weighted aggregation accumulator
__device__ float g_x1[NN * FF];
__device__ float g_x2[NN * FF];
__device__ float g_x3[NN * FF];
__device__ float g_es[NN];
__device__ float g_ed[NN];
__device__ float g_m[NN];
__device__ float g_den[NN];
__device__ float g_e[ET];
__device__ int   g_src[ET];
__device__ int   g_dst[ET];
__device__ float g_pool[GG * 3 * FF];
__device__ float g_cnt[GG];
__device__ int   g_is64;

// ---------------- index-width detection ----------------
// Reference declares int64, but JAX without x64 emits int32. Detect on-device:
// viewing an int64 array of values < 2^31 as int32, every odd word is 0.
__global__ void k_detect(const int* __restrict__ p) {
    __shared__ int any;
    if (threadIdx.x == 0) any = 0;
    __syncthreads();
    for (int i = threadIdx.x; i < 4096; i += blockDim.x)
        if (p[2 * i + 1] != 0) any = 1;
    __syncthreads();
    if (threadIdx.x == 0) g_is64 = !any;
}

__global__ void k_prep(const void* __restrict__ ei) {
    int i = blockIdx.x * blockDim.x + threadIdx.x;
    if (i >= ET) return;
    if (i < EE) {
        int s, d;
        if (g_is64) {
            const long long* e = (const long long*)ei;
            s = (int)e[i]; d = (int)e[EE + i];
        } else {
            const int* e = (const int*)ei;
            s = e[i]; d = e[EE + i];
        }
        g_src[i] = s; g_dst[i] = d;
    } else {
        g_src[i] = i - EE; g_dst[i] = i - EE;  // self loops
    }
}

__global__ void k_zero_pool() {
    int i = blockIdx.x * blockDim.x + threadIdx.x;
    if (i < GG * 3 * FF) g_pool[i] = 0.f;
    if (i < GG) g_cnt[i] = 0.f;
}

// ---------------- h = x @ W, per-node attention scores, init per-node state ----
template <int K>
__global__ void k_gemm(const float* __restrict__ xext, int which,
                       const float* __restrict__ W,
                       const float* __restrict__ as_, const float* __restrict__ ad_) {
    const float* x = (which == 0) ? xext : (which == 1) ? g_x1 : g_x2;
    int n = blockIdx.x, f = threadIdx.x;
    __shared__ float xs[K];
    for (int k = f; k < K; k += FF) xs[k] = x[(size_t)n * K + k];
    __syncthreads();
    float a = 0.f;
#pragma unroll
    for (int k = 0; k < K; k++) a += xs[k] * W[k * FF + f];
    g_h[n * FF + f] = a;
    g_acc[n * FF + f] = 0.f;

    __shared__ float r1[FF], r2[FF];
    r1[f] = a * as_[f];
    r2[f] = a * ad_[f];
    __syncthreads();
#pragma unroll
    for (int s = FF / 2; s > 0; s >>= 1) {
        if (f < s) { r1[f] += r1[f + s]; r2[f] += r2[f + s]; }
        __syncthreads();
    }
    if (f == 0) {
        g_es[n] = r1[0]; g_ed[n] = r2[0];
        g_m[n] = -INFINITY; g_den[n] = 0.f;
    }
}

// ---------------- segment softmax over incoming edges ----------------
__device__ __forceinline__ void atomicMaxF(float* a, float v) {
    if (v >= 0.f) atomicMax((int*)a, __float_as_int(v));
    else          atomicMin((unsigned int*)a, __float_as_uint(v));
}

__global__ void k_edge_max() {
    int i = blockIdx.x * blockDim.x + threadIdx.x;
    if (i >= ET) return;
    int s = g_src[i], d = g_dst[i];
    float e = g_es[s] + g_ed[d];
    e = e > 0.f ? e : 0.2f * e;  // leaky relu, slope 0.2
    g_e[i] = e;
    atomicMaxF(&g_m[d], e);
}

__global__ void k_edge_exp() {
    int i = blockIdx.x * blockDim.x + threadIdx.x;
    if (i >= ET) return;
    int d = g_dst[i];
    float p = __expf(g_e[i] - g_m[d]);
    g_e[i] = p;
    atomicAdd(&g_den[d], p);
}

// ---------------- weighted scatter: acc[dst] += alpha * h[src] ----------------
// 16 threads per edge, float4 each.
__global__ void k_scatter() {
    int t = blockIdx.x * blockDim.x + threadIdx.x;
    int edge = t >> 4;
    if (edge >= ET) return;
    int fq = (t & 15) << 2;
    int s = g_src[edge], d = g_dst[edge];
    float alpha = g_e[edge] / (g_den[d] + 1e-16f);
    const float4 hv = *(const float4*)&g_h[s * FF + fq];
    float* p = &g_acc[d * FF + fq];
    atomicAdd(p + 0, alpha * hv.x);
    atomicAdd(p + 1, alpha * hv.y);
    atomicAdd(p + 2, alpha * hv.z);
    atomicAdd(p + 3, alpha * hv.w);
}

__global__ void k_relu_bias(const float* __restrict__ b, int which) {
    int i = blockIdx.x * blockDim.x + threadIdx.x;
    if (i >= NN * FF) return;
    float v = g_acc[i] + b[i & (FF - 1)];
    v = v > 0.f ? v : 0.f;
    float* dst = (which == 1) ? g_x1 : (which == 2) ? g_x2 : g_x3;
    dst[i] = v;
}

// ---------------- mean pool over graphs ----------------
__global__ void k_pool(const void* __restrict__ batch) {
    int i = blockIdx.x * blockDim.x + threadIdx.x;
    if (i >= NN * 3 * FF) return;
    int n = i / (3 * FF);
    int f = i - n * (3 * FF);
    float v = (f < FF) ? g_x1[n * FF + f]
            : (f < 2 * FF) ? g_x2[n * FF + f - FF]
            : g_x3[n * FF + f - 2 * FF];
    int g = g_is64 ? (int)((const long long*)batch)[n] : ((const int*)batch)[n];
    atomicAdd(&g_pool[g * 3 * FF + f], v);
    if (f == 0) atomicAdd(&g_cnt[g], 1.f);
}

// ---------------- classifier + softmax ----------------
__global__ void k_classify(const float* __restrict__ Wo, const float* __restrict__ bo,
                           float* __restrict__ out) {
    int g = blockIdx.x * blockDim.x + threadIdx.x;
    if (g >= GG) return;
    float cnt = g_cnt[g]; if (cnt < 1.f) cnt = 1.f;
    float lg[CC];
#pragma unroll
    for (int c = 0; c < CC; c++) lg[c] = bo[c];
    for (int f = 0; f < 3 * FF; f++) {
        float p = g_pool[g * 3 * FF + f] / cnt;
#pragma unroll
        for (int c = 0; c < CC; c++) lg[c] += p * Wo[f * CC + c];
    }
    float mx = lg[0];
#pragma unroll
    for (int c = 1; c < CC; c++) mx = fmaxf(mx, lg[c]);
    float sum = 0.f;
#pragma unroll
    for (int c = 0; c < CC; c++) { lg[c] = expf(lg[c] - mx); sum += lg[c]; }
#pragma unroll
    for (int c = 0; c < CC; c++) out[g * CC + c] = lg[c] / sum;
}

// ---------------- launch ----------------
extern "C" void kernel_launch(void* const* d_in, const int* in_sizes, int n_in,
                              void* d_out, int out_size) {
    const float* x   = (const float*)d_in[0];
    const void*  ei  = d_in[1];
    const void*  bat = d_in[2];
    const float* W1  = (const float*)d_in[3];
    const float* a1s = (const float*)d_in[4];
    const float* a1d = (const float*)d_in[5];
    const float* b1  = (const float*)d_in[6];
    const float* W2  = (const float*)d_in[7];
    const float* a2s = (const float*)d_in[8];
    const float* a2d = (const float*)d_in[9];
    const float* b2  = (const float*)d_in[10];
    const float* W3  = (const float*)d_in[11];
    const float* a3s = (const float*)d_in[12];
    const float* a3d = (const float*)d_in[13];
    const float* b3  = (const float*)d_in[14];
    const float* Wo  = (const float*)d_in[15];
    const float* bo  = (const float*)d_in[16];
    float* out = (float*)d_out;

    const int TB = 256;
    const int EB = (ET + TB - 1) / TB;
    const int SB = (ET * 16 + TB - 1) / TB;
    const int RB = (NN * FF + TB - 1) / TB;

    k_detect<<<1, 256>>>((const int*)ei);
    k_prep<<<EB, TB>>>(ei);
    k_zero_pool<<<(GG * 3 * FF + TB - 1) / TB, TB>>>();

    // layer 1
    k_gemm<DIN><<<NN, FF>>>(x, 0, W1, a1s, a1d);
    k_edge_max<<<EB, TB>>>();
    k_edge_exp<<<EB, TB>>>();
    k_scatter<<<SB, TB>>>();
    k_relu_bias<<<RB, TB>>>(b1, 1);

    // layer 2
    k_gemm<FF><<<NN, FF>>>(nullptr, 1, W2, a2s, a2d);
    k_edge_max<<<EB, TB>>>();
    k_edge_exp<<<EB, TB>>>();
    k_scatter<<<SB, TB>>>();
    k_relu_bias<<<RB, TB>>>(b2, 2);

    // layer 3
    k_gemm<FF><<<NN, FF>>>(nullptr, 2, W3, a3s, a3d);
    k_edge_max<<<EB, TB>>>();
    k_edge_exp<<<EB, TB>>>();
    k_scatter<<<SB, TB>>>();
    k_relu_bias<<<RB, TB>>>(b3, 3);

    k_pool<<<(NN * 3 * FF + TB - 1) / TB, TB>>>(bat);
    k_classify<<<(GG + TB - 1) / TB, TB>>>(Wo, bo, out);
}

// round 11
// speedup vs baseline: 1.8750x; 1.8750x over previous
#include <cuda_runtime.h>
#include <math.h>

#define NN 100000
#define EE 1600000
#define ET 1700000   // EE + NN self loops
#define DIN 128
#define FF 64
#define GG 512
#define CC 10

// ---------------- scratch (device globals; no allocation) ----------------
__device__ float g_h[NN * FF];     // current layer transformed features
__device__ float g_x1[NN * FF];
__device__ float g_x2[NN * FF];
__device__ float g_x3[NN * FF];
__device__ float g_es[NN];
__device__ float g_ed[NN];
__device__ int   g_src[ET];
__device__ int   g_dst[ET];
__device__ int   g_csr[ET];        // src indices grouped by dst (CSR)
__device__ int   g_row[NN + 1];    // CSR row offsets
__device__ int   g_deg[NN];
__device__ int   g_cur[NN];
__device__ float g_pool[GG * 3 * FF];
__device__ float g_cnt[GG];
__device__ int   g_is64;

// ---------------- index-width detection ----------------
// Reference declares int64, but JAX without x64 emits int32. Detect on-device.
__global__ void k_detect(const int* __restrict__ p) {
    __shared__ int any;
    if (threadIdx.x == 0) any = 0;
    __syncthreads();
    for (int i = threadIdx.x; i < 4096; i += blockDim.x)
        if (p[2 * i + 1] != 0) any = 1;
    __syncthreads();
    if (threadIdx.x == 0) g_is64 = !any;
}

__global__ void k_zero() {
    int i = blockIdx.x * blockDim.x + threadIdx.x;
    if (i < NN) g_deg[i] = 0;
    if (i < GG * 3 * FF) g_pool[i] = 0.f;
    if (i < GG) g_cnt[i] = 0.f;
}

// decode edges, append self loops, histogram dst degrees
__global__ void k_prep(const void* __restrict__ ei) {
    int i = blockIdx.x * blockDim.x + threadIdx.x;
    if (i >= ET) return;
    int s, d;
    if (i < EE) {
        if (g_is64) {
            const long long* e = (const long long*)ei;
            s = (int)e[i]; d = (int)e[EE + i];
        } else {
            const int* e = (const int*)ei;
            s = e[i]; d = e[EE + i];
        }
    } else {
        s = i - EE; d = i - EE;  // self loops
    }
    g_src[i] = s; g_dst[i] = d;
    atomicAdd(&g_deg[d], 1);
}

// single-block raking exclusive scan of g_deg -> g_row, g_cur
__global__ void k_scan() {
    __shared__ int sums[1024];
    int t = threadIdx.x;
    const int CH = (NN + 1023) / 1024;
    int beg = t * CH, end = min(beg + CH, NN);
    int s = 0;
    for (int i = beg; i < end; i++) s += g_deg[i];
    sums[t] = s;
    __syncthreads();
    for (int o = 1; o < 1024; o <<= 1) {
        int v = (t >= o) ? sums[t - o] : 0;
        __syncthreads();
        sums[t] += v;
        __syncthreads();
    }
    int off = (t == 0) ? 0 : sums[t - 1];
    for (int i = beg; i < end; i++) {
        g_row[i] = off; g_cur[i] = off; off += g_deg[i];
    }
    if (t == 1023) g_row[NN] = sums[1023];
}

__global__ void k_fill() {
    int i = blockIdx.x * blockDim.x + threadIdx.x;
    if (i >= ET) return;
    int d = g_dst[i];
    int pos = atomicAdd(&g_cur[d], 1);
    g_csr[pos] = g_src[i];
}

// ---------------- h = x @ W + per-node attention scores ----------------
// 4 nodes per block, 64 threads. xsT staged transposed so the inner loop is
// one LDS.128 + one W load per 4 FFMAs.
template <int K>
__global__ void k_gemm(const float* __restrict__ xext, int which,
                       const float* __restrict__ W,
                       const float* __restrict__ as_, const float* __restrict__ ad_) {
    const float* x = (which == 0) ? xext : (which == 1) ? g_x1 : g_x2;
    int n0 = blockIdx.x * 4;
    int f = threadIdx.x;
    __shared__ float xsT[K][4];
    for (int idx = f; idx < 4 * K; idx += FF) {
        int r = idx / K, c = idx - r * K;
        xsT[c][r] = x[(size_t)(n0 + r) * K + c];
    }
    __syncthreads();
    float a0 = 0.f, a1 = 0.f, a2 = 0.f, a3 = 0.f;
#pragma unroll
    for (int k = 0; k < K; k++) {
        float w = W[k * FF + f];
        float4 xv = *(const float4*)&xsT[k][0];
        a0 += xv.x * w; a1 += xv.y * w; a2 += xv.z * w; a3 += xv.w * w;
    }
    g_h[(n0 + 0) * FF + f] = a0;
    g_h[(n0 + 1) * FF + f] = a1;
    g_h[(n0 + 2) * FF + f] = a2;
    g_h[(n0 + 3) * FF + f] = a3;

    __shared__ float r1[4][FF], r2[4][FF];
    float av = as_[f], dv = ad_[f];
    r1[0][f] = a0 * av; r2[0][f] = a0 * dv;
    r1[1][f] = a1 * av; r2[1][f] = a1 * dv;
    r1[2][f] = a2 * av; r2[2][f] = a2 * dv;
    r1[3][f] = a3 * av; r2[3][f] = a3 * dv;
    __syncthreads();
#pragma unroll
    for (int s = FF / 2; s > 0; s >>= 1) {
        if (f < s) {
#pragma unroll
            for (int i = 0; i < 4; i++) {
                r1[i][f] += r1[i][f + s];
                r2[i][f] += r2[i][f + s];
            }
        }
        __syncthreads();
    }
    if (f < 4) g_es[n0 + f] = r1[f][0];
    else if (f < 8) g_ed[n0 + f - 4] = r2[f - 4][0];
}

// ---------------- fused segment softmax + weighted gather + bias + relu ----
// One warp per dst node. Pass 1: warp-max of scores. Pass 2: register
// accumulation of denom and sum p*h[src]; divide once at the end. No atomics.
__global__ void k_gather(const float* __restrict__ b, int which) {
    int n = (blockIdx.x * blockDim.x + threadIdx.x) >> 5;
    if (n >= NN) return;
    int lane = threadIdx.x & 31;
    int beg = g_row[n], end = g_row[n + 1];
    float edn = g_ed[n];

    // pass 1: segment max
    float m = -INFINITY;
    for (int j = beg + lane; j < end; j += 32) {
        int s = g_csr[j];
        float e = g_es[s] + edn;
        e = e > 0.f ? e : 0.2f * e;
        m = fmaxf(m, e);
    }
#pragma unroll
    for (int o = 16; o; o >>= 1) m = fmaxf(m, __shfl_xor_sync(0xffffffffu, m, o));

    // pass 2: denom + weighted accumulation
    float acc0 = 0.f, acc1 = 0.f, den = 0.f;
    for (int j0 = beg; j0 < end; j0 += 32) {
        int j = j0 + lane;
        int s = 0; float p = 0.f;
        if (j < end) {
            s = g_csr[j];
            float e = g_es[s] + edn;
            e = e > 0.f ? e : 0.2f * e;
            p = __expf(e - m);
        }
        den += p;
        int cnt = min(32, end - j0);
        for (int k = 0; k < cnt; k++) {
            int   sk = __shfl_sync(0xffffffffu, s, k);
            float pk = __shfl_sync(0xffffffffu, p, k);
            const float* hp = &g_h[sk * FF];
            acc0 += pk * hp[lane];
            acc1 += pk * hp[lane + 32];
        }
    }
#pragma unroll
    for (int o = 16; o; o >>= 1) den += __shfl_xor_sync(0xffffffffu, den, o);
    float inv = 1.f / (den + 1e-16f);

    float v0 = acc0 * inv + b[lane];
    float v1 = acc1 * inv + b[lane + 32];
    v0 = v0 > 0.f ? v0 : 0.f;
    v1 = v1 > 0.f ? v1 : 0.f;
    float* dst = (which == 1) ? g_x1 : (which == 2) ? g_x2 : g_x3;
    dst[n * FF + lane] = v0;
    dst[n * FF + 32 + lane] = v1;
}

// ---------------- mean pool over graphs ----------------
__global__ void k_pool(const void* __restrict__ batch) {
    int i = blockIdx.x * blockDim.x + threadIdx.x;
    if (i >= NN * 3 * FF) return;
    int n = i / (3 * FF);
    int f = i - n * (3 * FF);
    float v = (f < FF) ? g_x1[n * FF + f]
            : (f < 2 * FF) ? g_x2[n * FF + f - FF]
            : g_x3[n * FF + f - 2 * FF];
    int g = g_is64 ? (int)((const long long*)batch)[n] : ((const int*)batch)[n];
    atomicAdd(&g_pool[g * 3 * FF + f], v);
    if (f == 0) atomicAdd(&g_cnt[g], 1.f);
}

// ---------------- classifier + softmax ----------------
__global__ void k_classify(const float* __restrict__ Wo, const float* __restrict__ bo,
                           float* __restrict__ out) {
    int g = blockIdx.x * blockDim.x + threadIdx.x;
    if (g >= GG) return;
    float cnt = g_cnt[g]; if (cnt < 1.f) cnt = 1.f;
    float lg[CC];
#pragma unroll
    for (int c = 0; c < CC; c++) lg[c] = bo[c];
    for (int f = 0; f < 3 * FF; f++) {
        float p = g_pool[g * 3 * FF + f] / cnt;
#pragma unroll
        for (int c = 0; c < CC; c++) lg[c] += p * Wo[f * CC + c];
    }
    float mx = lg[0];
#pragma unroll
    for (int c = 1; c < CC; c++) mx = fmaxf(mx, lg[c]);
    float sum = 0.f;
#pragma unroll
    for (int c = 0; c < CC; c++) { lg[c] = expf(lg[c] - mx); sum += lg[c]; }
#pragma unroll
    for (int c = 0; c < CC; c++) out[g * CC + c] = lg[c] / sum;
}

// ---------------- launch ----------------
extern "C" void kernel_launch(void* const* d_in, const int* in_sizes, int n_in,
                              void* d_out, int out_size) {
    const float* x   = (const float*)d_in[0];
    const void*  ei  = d_in[1];
    const void*  bat = d_in[2];
    const float* W1  = (const float*)d_in[3];
    const float* a1s = (const float*)d_in[4];
    const float* a1d = (const float*)d_in[5];
    const float* b1  = (const float*)d_in[6];
    const float* W2  = (const float*)d_in[7];
    const float* a2s = (const float*)d_in[8];
    const float* a2d = (const float*)d_in[9];
    const float* b2  = (const float*)d_in[10];
    const float* W3  = (const float*)d_in[11];
    const float* a3s = (const float*)d_in[12];
    const float* a3d = (const float*)d_in[13];
    const float* b3  = (const float*)d_in[14];
    const float* Wo  = (const float*)d_in[15];
    const float* bo  = (const float*)d_in[16];
    float* out = (float*)d_out;

    const int TB = 256;
    const int EB = (ET + TB - 1) / TB;
    const int GB = (NN * 32 + TB - 1) / TB;   // warp per node

    k_detect<<<1, 256>>>((const int*)ei);
    k_zero<<<(NN + TB - 1) / TB, TB>>>();
    k_prep<<<EB, TB>>>(ei);
    k_scan<<<1, 1024>>>();
    k_fill<<<EB, TB>>>();

    // layer 1
    k_gemm<DIN><<<NN / 4, FF>>>(x, 0, W1, a1s, a1d);
    k_gather<<<GB, TB>>>(b1, 1);

    // layer 2
    k_gemm<FF><<<NN / 4, FF>>>(nullptr, 1, W2, a2s, a2d);
    k_gather<<<GB, TB>>>(b2, 2);

    // layer 3
    k_gemm<FF><<<NN / 4, FF>>>(nullptr, 2, W3, a3s, a3d);
    k_gather<<<GB, TB>>>(b3, 3);

    k_pool<<<(NN * 3 * FF + TB - 1) / TB, TB>>>(bat);
    k_classify<<<(GG + TB - 1) / TB, TB>>>(Wo, bo, out);
}